// round 5
// baseline (speedup 1.0000x reference)
#include <cuda_runtime.h>
#include <cuda_bf16.h>
#include <cuda_fp8.h>

// ---------------------------------------------------------------------------
// Problem constants
// ---------------------------------------------------------------------------
#define M_TOTAL 16384   // 16 * 1024 query rows
#define N_CODES 8192
#define K_DIM   256
#define NUMEL   (M_TOTAL * K_DIM)   // 4194304

#define BM 128           // CTA M rows
#define BN 128           // codes per N-tile
#define NT_TILES (N_CODES / BN)     // 64
#define TOPK 8           // refined candidates per row
#define LANE_TOP 3       // per-lane candidate depth
#define NCAND 48         // 16 lane-groups x 3 per row

// E is scaled by 256 (exact) before fp8 conversion; dist = esq - acc/128.
#define INV_SCALE (-0.0078125f)   // -2 * 2^-8

// SMEM layout (dynamic):  A 32KB | B0 32KB | B1 32KB | esq0/esq1
#define SM_A     0
#define SM_B0    32768
#define SM_B1    65536
#define SM_ESQ0  98304
#define SM_ESQ1  98816
#define SM_TOTAL 99328
// candidate merge buffers alias the B region after the main loop
#define SM_CV    32768                  // float [128][48] = 24576 B
#define SM_CI    (32768 + 24576)        // int   [128][48] = 24576 B

// ---------------------------------------------------------------------------
// Scratch (no dynamic device allocation allowed)
// ---------------------------------------------------------------------------
__device__ float         g_esq[N_CODES];
__device__ float         g_qsq[M_TOTAL];
__device__ int           g_idx[M_TOTAL];
__device__ int           g_cand[M_TOTAL][TOPK];
__device__ unsigned char g_E_fp8[N_CODES * K_DIM];   // e4m3, scaled x256
__device__ unsigned char g_Q_fp8[M_TOTAL * K_DIM];   // e4m3
__device__ double        g_loss;

// ---------------------------------------------------------------------------
// Baseline-PTX helpers (sm_89-level features only: mma/ldmatrix/cp.async)
// ---------------------------------------------------------------------------
__device__ __forceinline__ unsigned smem_u32(const void* p) {
    unsigned a;
    asm("{ .reg .u64 t; cvta.to.shared.u64 t, %1; cvt.u32.u64 %0, t; }"
        : "=r"(a) : "l"(p));
    return a;
}

#define LDSM_X4(r, addr) \
    asm volatile("ldmatrix.sync.aligned.m8n8.x4.shared.b16 {%0,%1,%2,%3}, [%4];" \
        : "=r"((r)[0]), "=r"((r)[1]), "=r"((r)[2]), "=r"((r)[3]) : "r"(addr))

#define MMA16832(c, a, b0, b1) \
    asm volatile("mma.sync.aligned.m16n8k32.row.col.f32.e4m3.e4m3.f32 " \
        "{%0,%1,%2,%3}, {%4,%5,%6,%7}, {%8,%9}, {%0,%1,%2,%3};" \
        : "+f"((c)[0]), "+f"((c)[1]), "+f"((c)[2]), "+f"((c)[3]) \
        : "r"((a)[0]), "r"((a)[1]), "r"((a)[2]), "r"((a)[3]), "r"(b0), "r"(b1))

__device__ __forceinline__ void cp16(unsigned dst, const void* src) {
    asm volatile("cp.async.cg.shared.global [%0], [%1], 16;"
                 :: "r"(dst), "l"(src));
}
#define CP_COMMIT()  asm volatile("cp.async.commit_group;" ::: "memory")
#define CP_WAIT_1()  asm volatile("cp.async.wait_group 1;" ::: "memory")
#define CP_WAIT_0()  asm volatile("cp.async.wait_group 0;" ::: "memory")

// ---------------------------------------------------------------------------
// Kernel 1a: e_sq[n] + zero loss accumulator (order kept from passing rounds)
// ---------------------------------------------------------------------------
__global__ void esq_kernel(const float* __restrict__ emb) {
    if (blockIdx.x == 0 && threadIdx.x == 0 && threadIdx.y == 0) g_loss = 0.0;
    int row = blockIdx.x * 8 + threadIdx.y;
    const float* e = emb + (size_t)row * K_DIM;
    float s = 0.0f;
    #pragma unroll
    for (int j = 0; j < K_DIM / 32; j++) {
        float v = e[threadIdx.x + 32 * j];
        s = __fadd_rn(s, __fmul_rn(v, v));
    }
    #pragma unroll
    for (int o = 16; o > 0; o >>= 1)
        s = __fadd_rn(s, __shfl_down_sync(0xffffffffu, s, o));
    if (threadIdx.x == 0) g_esq[row] = s;
}

// ---------------------------------------------------------------------------
// Kernel 1b: q_sq[m] — XLA-order row reduction (bit-exact; DO NOT CHANGE)
// ---------------------------------------------------------------------------
__global__ void qsq_kernel(const float* __restrict__ q) {
    int row = blockIdx.x * 8 + threadIdx.y;
    const float* x = q + (size_t)row * K_DIM;
    float s = 0.0f;
    #pragma unroll
    for (int j = 0; j < K_DIM / 32; j++) {
        float v = x[threadIdx.x + 32 * j];
        s = __fadd_rn(s, __fmul_rn(v, v));
    }
    #pragma unroll
    for (int o = 16; o > 0; o >>= 1)
        s = __fadd_rn(s, __shfl_down_sync(0xffffffffu, s, o));
    if (threadIdx.x == 0) g_qsq[row] = s;
}

// ---------------------------------------------------------------------------
// Kernel 1c/1d: f32 -> e4m3 conversions (E scaled x256 to clear subnormals)
// ---------------------------------------------------------------------------
__global__ void convert_e_kernel(const float* __restrict__ E) {
    int i = blockIdx.x * 256 + threadIdx.x;     // over N*K/4 float4
    float4 v = ((const float4*)E)[i];
    float2 lo = make_float2(v.x * 256.0f, v.y * 256.0f);
    float2 hi = make_float2(v.z * 256.0f, v.w * 256.0f);
    unsigned short p0 = __nv_cvt_float2_to_fp8x2(lo, __NV_SATFINITE, __NV_E4M3);
    unsigned short p1 = __nv_cvt_float2_to_fp8x2(hi, __NV_SATFINITE, __NV_E4M3);
    ((unsigned*)g_E_fp8)[i] = (unsigned)p0 | ((unsigned)p1 << 16);
}
__global__ void convert_q_kernel(const float* __restrict__ Q) {
    int i = blockIdx.x * 256 + threadIdx.x;     // over M*K/4 float4
    float4 v = ((const float4*)Q)[i];
    float2 lo = make_float2(v.x, v.y);
    float2 hi = make_float2(v.z, v.w);
    unsigned short p0 = __nv_cvt_float2_to_fp8x2(lo, __NV_SATFINITE, __NV_E4M3);
    unsigned short p1 = __nv_cvt_float2_to_fp8x2(hi, __NV_SATFINITE, __NV_E4M3);
    ((unsigned*)g_Q_fp8)[i] = (unsigned)p0 | ((unsigned)p1 << 16);
}

// ---------------------------------------------------------------------------
// Kernel 2: e4m3 mma.sync GEMM + per-row candidate tracking.
// CTA: 128 query rows, 256 threads = 8 warps (2 M x 4 N), warp tile 64x32.
// approx dist(m,n) = esq[n] - acc/128   (E scaled x256; qsq per-row const).
// Each lane keeps top-3 per owned row; 16 lane-groups/row -> 48 candidates
// merged in SMEM to top-8 -> g_cand.
// ---------------------------------------------------------------------------
__global__ __launch_bounds__(256, 1) void gemm_topk_kernel() {
    extern __shared__ char smem[];
    const unsigned sbase = smem_u32(smem);
    const int tid    = threadIdx.x;
    const int lane   = tid & 31;
    const int wid    = tid >> 5;
    const int warp_m = wid >> 2;          // 0..1
    const int warp_n = wid & 3;           // 0..3
    const int m0     = blockIdx.x * BM;

    // ---- stage A (rows 256 B = 16 granules; swizzle g' = g ^ (row&7)) ----
    {
        const uint4* Aq = (const uint4*)(g_Q_fp8 + (size_t)m0 * K_DIM);
        #pragma unroll
        for (int it = 0; it < 8; it++) {
            int i   = it * 256 + tid;     // 2048 granules
            int row = i >> 4;
            int g   = i & 15;
            uint4 v = Aq[row * 16 + g];
            *(uint4*)(smem + SM_A + row * 256 + ((g ^ (row & 7)) << 4)) = v;
        }
    }

    // ---- B tile async loader ----
    auto issue_B = [&](int t, int buf) {
        const uint4* Bq = (const uint4*)(g_E_fp8 + (size_t)t * BN * K_DIM);
        unsigned bb = sbase + SM_B0 + buf * 32768;
        #pragma unroll
        for (int it = 0; it < 8; it++) {
            int i   = it * 256 + tid;
            int row = i >> 4;
            int g   = i & 15;
            cp16(bb + row * 256 + ((g ^ (row & 7)) << 4), Bq + row * 16 + g);
        }
        if (tid < BN)
            *(float*)(smem + SM_ESQ0 + buf * 512 + tid * 4) = g_esq[t * BN + tid];
    };

    issue_B(0, 0);
    CP_COMMIT();

    // ldmatrix lane-invariant address pieces (same pattern as the validated
    // bf16 kernel; fp8 k32 fragment == bf16 k16 fragment with b16 -> 2x e4m3)
    const int j       = lane >> 3;
    const int a_rloc  = (j & 1) * 8 + (lane & 7);   // row-in-16 for A frags
    const int a_khalf = (j >> 1);                   // k 16-granule half
    const int b_rloc  = (j >> 1) * 8 + (lane & 7);  // row-in-16 for B frags
    const int b_khalf = (j & 1);
    const unsigned aRowBase = sbase + SM_A + (unsigned)(warp_m * 64 + a_rloc) * 256;

    // per-lane, per-row top-3
    float v1[8], v2[8], v3[8];
    int   i1[8], i2[8], i3[8];
    #pragma unroll
    for (int r = 0; r < 8; r++) {
        v1[r] = 3.4e38f; v2[r] = 3.4e38f; v3[r] = 3.4e38f;
        i1[r] = 0; i2[r] = 0; i3[r] = 0;
    }

    for (int t = 0; t < NT_TILES; t++) {
        const int nb = t & 1;
        if (t + 1 < NT_TILES) {
            issue_B(t + 1, nb ^ 1);
            CP_COMMIT();
            CP_WAIT_1();
        } else {
            CP_WAIT_0();
        }
        __syncthreads();   // tile t visible; previous tile's readers done

        const unsigned sB = sbase + SM_B0 + nb * 32768 + (unsigned)(warp_n * 32) * 256;
        const float* sE = (const float*)(smem + SM_ESQ0 + nb * 512);

        float acc[4][4][4];
        #pragma unroll
        for (int mt = 0; mt < 4; mt++)
            #pragma unroll
            for (int nt = 0; nt < 4; nt++)
                #pragma unroll
                for (int c = 0; c < 4; c++) acc[mt][nt][c] = 0.0f;

        #pragma unroll
        for (int ks = 0; ks < 8; ks++) {       // K = 8 x 32
            const unsigned swzA = (unsigned)(((2 * ks + a_khalf) ^ (lane & 7)) << 4);
            const unsigned swzB = (unsigned)(((2 * ks + b_khalf) ^ (lane & 7)) << 4);

            unsigned a[4][4];
            #pragma unroll
            for (int mt = 0; mt < 4; mt++)
                LDSM_X4(a[mt], aRowBase + (unsigned)(mt * 16) * 256 + swzA);

            unsigned b[2][4];
            #pragma unroll
            for (int nt2 = 0; nt2 < 2; nt2++)
                LDSM_X4(b[nt2], sB + (unsigned)(nt2 * 16 + b_rloc) * 256 + swzB);

            #pragma unroll
            for (int mt = 0; mt < 4; mt++) {
                MMA16832(acc[mt][0], a[mt], b[0][0], b[0][1]);
                MMA16832(acc[mt][1], a[mt], b[0][2], b[0][3]);
                MMA16832(acc[mt][2], a[mt], b[1][0], b[1][1]);
                MMA16832(acc[mt][3], a[mt], b[1][2], b[1][3]);
            }
        }

        // ---- epilogue: per-lane top-3 tracking ----
        #pragma unroll
        for (int nt = 0; nt < 4; nt++) {
            const int cbase = warp_n * 32 + nt * 8 + ((lane & 3) << 1);
            const float e0 = sE[cbase];
            const float e1 = sE[cbase + 1];
            const int n0 = t * BN + cbase;
            #pragma unroll
            for (int mt = 0; mt < 4; mt++) {
                #pragma unroll
                for (int c = 0; c < 4; c++) {
                    const int r   = mt * 2 + (c >> 1);
                    const float d = fmaf(acc[mt][nt][c], INV_SCALE, (c & 1) ? e1 : e0);
                    const int  n  = n0 + (c & 1);
                    if (d < v3[r]) {
                        if (d < v2[r]) {
                            v3[r] = v2[r]; i3[r] = i2[r];
                            if (d < v1[r]) {
                                v2[r] = v1[r]; i2[r] = i1[r];
                                v1[r] = d;     i1[r] = n;
                            } else { v2[r] = d; i2[r] = n; }
                        } else { v3[r] = d; i3[r] = n; }
                    }
                }
            }
        }
        __syncthreads();   // done reading sB/sE before overwrite
    }

    // ---- merge: 48 candidates/row -> top-8 ----
    float* cv = (float*)(smem + SM_CV);   // [128][48]
    int*   ci = (int*)(smem + SM_CI);     // [128][48]
    #pragma unroll
    for (int r = 0; r < 8; r++) {
        const int mt = r >> 1, hi = r & 1;
        const int row  = warp_m * 64 + mt * 16 + hi * 8 + (lane >> 2);
        const int slot = warp_n * 12 + (lane & 3) * 3;
        cv[row * NCAND + slot]     = v1[r];  ci[row * NCAND + slot]     = i1[r];
        cv[row * NCAND + slot + 1] = v2[r];  ci[row * NCAND + slot + 1] = i2[r];
        cv[row * NCAND + slot + 2] = v3[r];  ci[row * NCAND + slot + 2] = i3[r];
    }
    __syncthreads();
    if (tid < BM) {
        const int row = tid;
        float bv[TOPK];
        int   bi[TOPK];
        #pragma unroll
        for (int s = 0; s < TOPK; s++) { bv[s] = 3.4e38f; bi[s] = 0; }
        for (int s = 0; s < NCAND; s++) {
            const float v = cv[row * NCAND + s];
            const int   n = ci[row * NCAND + s];
            if (v < bv[TOPK - 1]) {
                int p = TOPK - 1;
                #pragma unroll
                for (int q = TOPK - 1; q > 0; q--) {
                    if (v < bv[q - 1]) {
                        bv[q] = bv[q - 1]; bi[q] = bi[q - 1]; p = q - 1;
                    }
                }
                bv[p] = v; bi[p] = n;
            }
        }
        #pragma unroll
        for (int c = 0; c < TOPK; c++) g_cand[m0 + row][c] = bi[c];
    }
}

// ---------------------------------------------------------------------------
// Kernel 3: exact refine of TOPK candidates (bit-exact round-2 arithmetic:
// ascending-k fmaf, reference f32 grid emulation, lowest-index tie-break).
// ---------------------------------------------------------------------------
__global__ __launch_bounds__(128) void refine_kernel(
    const float* __restrict__ Q,
    const float* __restrict__ E,
    float* __restrict__ out_idx_f)
{
    int row = blockIdx.x * 128 + threadIdx.x;
    float qs = g_qsq[row];
    const float4* q = (const float4*)(Q + (size_t)row * K_DIM);
    float bestd = 3.4e38f;
    int   besti = 0x7fffffff;
    #pragma unroll
    for (int c = 0; c < TOPK; c++) {
        int n = g_cand[row][c];
        const float4* e = (const float4*)(E + (size_t)n * K_DIM);
        float acc = 0.0f;
        #pragma unroll 8
        for (int k = 0; k < K_DIM / 4; k++) {
            float4 qv = q[k];
            float4 ev = e[k];
            acc = fmaf(qv.x, ev.x, acc);
            acc = fmaf(qv.y, ev.y, acc);
            acc = fmaf(qv.z, ev.z, acc);
            acc = fmaf(qv.w, ev.w, acc);
        }
        float d = __fsub_rn(__fadd_rn(qs, g_esq[n]), 2.0f * acc);
        if (d < bestd || (d == bestd && n < besti)) { bestd = d; besti = n; }
    }
    g_idx[row] = besti;
    out_idx_f[row] = (float)besti;
}

// ---------------------------------------------------------------------------
// Kernel 4: gather quantized = embedding[idx] + SSE for the loss.
// ---------------------------------------------------------------------------
__global__ __launch_bounds__(256) void gather_loss_kernel(
    const float* __restrict__ Q,
    const float* __restrict__ E,
    float* __restrict__ out)
{
    __shared__ float warp_s[8];
    const int r   = threadIdx.x >> 6;
    const int t   = threadIdx.x & 63;
    const int row = blockIdx.x * 4 + r;
    const int idx = g_idx[row];

    const float4* q = (const float4*)(Q + (size_t)row * K_DIM);
    const float4* e = (const float4*)(E + (size_t)idx * K_DIM);
    float4*       o = (float4*)(out + M_TOTAL + (size_t)row * K_DIM);

    float4 qv = q[t];
    float4 ev = e[t];
    o[t] = ev;

    float dx = qv.x - ev.x, dy = qv.y - ev.y, dz = qv.z - ev.z, dw = qv.w - ev.w;
    float s = dx * dx + dy * dy + dz * dz + dw * dw;

    #pragma unroll
    for (int off = 16; off > 0; off >>= 1)
        s += __shfl_down_sync(0xffffffffu, s, off);
    if ((threadIdx.x & 31) == 0) warp_s[threadIdx.x >> 5] = s;
    __syncthreads();
    if (threadIdx.x == 0) {
        float acc = 0.0f;
        #pragma unroll
        for (int w = 0; w < 8; w++) acc += warp_s[w];
        atomicAdd(&g_loss, (double)acc);
    }
}

// ---------------------------------------------------------------------------
// Kernel 5: finalize loss. vq = codebook + 0.25*commit = 1.25 * SSE / NUMEL
// ---------------------------------------------------------------------------
__global__ void finalize_kernel(float* __restrict__ out) {
    out[M_TOTAL + (size_t)NUMEL] = (float)(1.25 * g_loss / (double)NUMEL);
}

// ---------------------------------------------------------------------------
extern "C" void kernel_launch(void* const* d_in, const int* in_sizes, int n_in,
                              void* d_out, int out_size) {
    const float* Q = (const float*)d_in[0];   // queries   [16,1024,256]
    const float* E = (const float*)d_in[1];   // embedding [8192,256]
    float* out = (float*)d_out;

    static int configured = 0;
    if (!configured) {
        cudaFuncSetAttribute(gemm_topk_kernel,
                             cudaFuncAttributeMaxDynamicSharedMemorySize, SM_TOTAL);
        configured = 1;
    }

    esq_kernel<<<N_CODES / 8, dim3(32, 8)>>>(E);
    qsq_kernel<<<M_TOTAL / 8, dim3(32, 8)>>>(Q);
    convert_e_kernel<<<(N_CODES * K_DIM / 4) / 256, 256>>>(E);
    convert_q_kernel<<<(M_TOTAL * K_DIM / 4) / 256, 256>>>(Q);
    gemm_topk_kernel<<<M_TOTAL / BM, 256, SM_TOTAL>>>();
    refine_kernel<<<M_TOTAL / 128, 128>>>(Q, E, out);
    gather_loss_kernel<<<M_TOTAL / 4, 256>>>(Q, E, out);
    finalize_kernel<<<1, 1>>>(out);
}